// round 13
// baseline (speedup 1.0000x reference)
#include <cuda_runtime.h>
#include <cstdint>

#define Bn   32
#define Tn   64
#define Nn   128
#define Dn   64
#define Cn   129
#define CP   132
#define QDn  5
#define NEn  8
#define PLMn 768
#define G3   192
#define NEGV (-9e15f)

#define WCOLS 352
#define WSTR  344
#define VROW  264
#define NCTA  128u
#define NT    512
#define PR    332

// ---------------- device scratch ----------------
__device__ __align__(16) float g_qv[Nn * QDn];
__device__ __align__(16) float g_ne[Nn * NEn];
__device__ __align__(16) float g_adj[Nn * Nn];
__device__ __align__(16) float g_rar[Bn * Tn * Nn];
__device__ __align__(16) float g_gW[Nn * Cn * G3];
__device__ __align__(16) float g_gB[Nn * G3];
__device__ __align__(16) float g_WT2[Cn * WCOLS];
__device__ __align__(16) float g_bT[WCOLS];
__device__ __align__(16) float g_Q[2 * Bn * Nn * 32];
__device__ __align__(16) float g_K[2 * Bn * Nn * 32];
__device__ __align__(16) float g_V[2 * (size_t)Bn * Nn * VROW];
__device__ __align__(16) float g_att[(size_t)Bn * Nn * CP];

__device__ unsigned g_ctrG;
__device__ unsigned g_ctrGrp[4];

// ---------------- helpers ----------------
#define FMA2(acc, w, z) asm("fma.rn.f32x2 %0, %1, %2, %0;" : "+l"(acc) : "l"(w), "l"(z))

__device__ __forceinline__ unsigned long long pk2(float z) {
    unsigned long long r;
    asm("mov.b64 %0, {%1, %1};" : "=l"(r) : "f"(z));
    return r;
}
__device__ __forceinline__ float2 up2(unsigned long long v) {
    float2 r;
    asm("mov.b64 {%0, %1}, %2;" : "=f"(r.x), "=f"(r.y) : "l"(v));
    return r;
}
__device__ __forceinline__ float f4c(const float4& v, int cc) {
    return cc == 0 ? v.x : cc == 1 ? v.y : cc == 2 ? v.z : v.w;
}
__device__ __forceinline__ void cpa16(unsigned dst, const void* src) {
    asm volatile("cp.async.cg.shared.global [%0], [%1], 16;" :: "r"(dst), "l"(src));
}
#define CP_COMMIT() asm volatile("cp.async.commit_group;" ::: "memory")
#define CP_WAIT(N)  asm volatile("cp.async.wait_group %0;" :: "n"(N) : "memory")

__device__ __forceinline__ float fsigmoid(float x) {
    return __fdividef(1.0f, 1.0f + __expf(-x));
}
__device__ __forceinline__ float ftanh(float x) {
    return 1.0f - 2.0f * __fdividef(1.0f, __expf(2.0f * x) + 1.0f);
}

// ---------------- precompute ----------------
__global__ void k_preA(const float* __restrict__ maskp, const float* __restrict__ avg,
                       const float* __restrict__ plm,
                       const float* __restrict__ pfW1, const float* __restrict__ pfb1,
                       const float* __restrict__ pfW2, const float* __restrict__ pfb2,
                       const float* __restrict__ pgW1, const float* __restrict__ pgb1,
                       const float* __restrict__ pgW2, const float* __restrict__ pgb2) {
    __shared__ float h1[128], h2[128];
    __shared__ float nrm;
    if (blockIdx.x < 32) {
        int b = blockIdx.x, n = threadIdx.x;
        int gtid = b * 128 + n;
        if (gtid == 0) g_ctrG = 0;
        if (gtid < 4)  g_ctrGrp[gtid] = 0;
        float s = 0.0f;
        for (int t = 0; t < Tn; t++) s += maskp[(b * Tn + t) * Nn + n];
        float inv = 1.0f / (s + 1.0f);
        for (int t = 0; t < Tn; t++)
            g_rar[(b * Tn + t) * Nn + n] = 0.5f * tanhf(avg[(b * Tn + t) * Nn + n] * inv);
        return;
    }
    int n = blockIdx.x - 32, j = threadIdx.x;
    const float* p = plm + (size_t)n * PLMn;
    float a = 0.0f, bv = 0.0f;
    for (int c = 0; c < PLMn; c++) {
        float pv = p[c];
        a  += pv * pfW1[c * 128 + j];
        bv += pv * pgW1[c * 128 + j];
    }
    a += pfb1[j]; bv += pgb1[j];
    h1[j] = a  > 0.0f ? a  : 0.0f;
    h2[j] = bv > 0.0f ? bv : 0.0f;
    __syncthreads();
    if (j < QDn) {
        float s = pfb2[j];
        for (int c = 0; c < 128; c++) s += h1[c] * pfW2[c * QDn + j];
        g_qv[n * QDn + j] = s;
    }
    if (j < NEn) {
        float s = pgb2[j];
        for (int c = 0; c < 128; c++) s += h2[c] * pgW2[c * NEn + j];
        g_ne[n * NEn + j] = s;
    }
    __syncthreads();
    if (j == 0) {
        float s = 0.0f;
        for (int e = 0; e < NEn; e++) { float v = g_ne[n * NEn + e]; s += v * v; }
        nrm = fmaxf(sqrtf(s), 1e-12f);
    }
    __syncthreads();
    if (j < NEn) g_ne[n * NEn + j] /= nrm;
}

__global__ void k_pre2() {
    int n = blockIdx.x, m = threadIdx.x;
    __shared__ float red[128];
    float s = 0.0f;
    for (int e = 0; e < NEn; e++) s += g_ne[n * NEn + e] * g_ne[m * NEn + e];
    red[m] = s;
    __syncthreads();
    for (int st = 64; st > 0; st >>= 1) { if (m < st) red[m] = fmaxf(red[m], red[m + st]); __syncthreads(); }
    float mx = red[0];
    __syncthreads();
    float e = expf(s - mx);
    red[m] = e;
    __syncthreads();
    for (int st = 64; st > 0; st >>= 1) { if (m < st) red[m] += red[m + st]; __syncthreads(); }
    g_adj[n * Nn + m] = e / red[0];
}

__global__ void k_preB(const float* __restrict__ rstW, const float* __restrict__ rstB,
                       const float* __restrict__ updW, const float* __restrict__ updB,
                       const float* __restrict__ candW, const float* __restrict__ candB,
                       const float* __restrict__ qW, const float* __restrict__ qb,
                       const float* __restrict__ kW, const float* __restrict__ kb,
                       const float* __restrict__ vW, const float* __restrict__ vb) {
    __shared__ float qv[QDn];
    if (blockIdx.x < 128) {
        int n = blockIdx.x;
        if (threadIdx.x < QDn) qv[threadIdx.x] = g_qv[n * QDn + threadIdx.x];
        __syncthreads();
        for (int idx = threadIdx.x; idx < Cn * Dn; idx += blockDim.x) {
            int c = idx / Dn, o = idx % Dn;
            float r = 0.0f, u = 0.0f, cd = 0.0f;
            for (int q = 0; q < QDn; q++) {
                float s = qv[q];
                int off = (q * Cn + c) * Dn + o;
                r  += s * rstW[off];
                u  += s * updW[off];
                cd += s * candW[off];
            }
            float* dst = g_gW + ((size_t)n * Cn + c) * G3;
            dst[o] = r; dst[64 + o] = u; dst[128 + o] = cd;
        }
        for (int o = threadIdx.x; o < Dn; o += blockDim.x) {
            float r = 0.0f, u = 0.0f, cd = 0.0f;
            for (int q = 0; q < QDn; q++) {
                float s = qv[q];
                r  += s * rstB[q * Dn + o];
                u  += s * updB[q * Dn + o];
                cd += s * candB[q * Dn + o];
            }
            g_gB[n * G3 + o] = r; g_gB[n * G3 + 64 + o] = u; g_gB[n * G3 + 128 + o] = cd;
        }
        return;
    }
    int c = blockIdx.x - 128;
    int j = threadIdx.x;
    float w = 0.0f, bv = 0.0f;
    if (j < 32) {
        int h = j >> 4, kk = j & 15;
        w = qW[(h * Cn + c) * 16 + kk]; bv = qb[h * 16 + kk];
    } else if (j < 64) {
        int jj = j - 32; int h = jj >> 4, kk = jj & 15;
        w = kW[(h * Cn + c) * 16 + kk]; bv = kb[h * 16 + kk];
    } else if (j <= 192) {
        int d = j - 64;
        w = vW[((size_t)c) * Cn + d]; bv = vb[d];
    } else if (j >= 196 && j <= 324) {
        int d = j - 196;
        w = vW[((size_t)(Cn + c)) * Cn + d]; bv = vb[Cn + d];
    }
    g_WT2[c * WCOLS + j] = w;
    if (c == 0) g_bT[j] = bv;
}

// ---------------- group barrier ----------------
__device__ __forceinline__ void gsync(unsigned* ctr, unsigned target) {
    __syncthreads();
    if (threadIdx.x == 0) {
        __threadfence();
        atomicAdd(ctr, 1u);
        while (*(volatile unsigned*)ctr < target) { }
        __threadfence();
    }
    __syncthreads();
}

// ---------------- smem layout (floats) ----------------
// OV  : permanent qkv weights 129 x 344
// SCR : per-phase scratch 10,880 floats
// HS  : resident h 32 x 66 ; SB : qkv bias
#define OV_F   (Cn * WSTR)              // 44376
#define SCR_F  10880
#define HS_OFF (OV_F + SCR_F)           // 55256
#define SB_OFF (HS_OFF + 2112)          // 57368
#define SMEM_FLOATS (SB_OFF + 328)      // 57696
#define SMEM_B (SMEM_FLOATS * 4)        // 230784 bytes

// C-phase ring offsets (within scr)
#define RING1_OFF 4224                  // 3 x 1024 (8c x 128 cols)
#define RING2_OFF 8544                  // 3 x 512  (8c x 64 cols)
#define GB_OFF    10080
#define MSK_OFF   10272

__global__ void __launch_bounds__(NT, 1) k_main(const float* __restrict__ obs,
                                                const float* __restrict__ maskp,
                                                const float* __restrict__ rarW,
                                                const int* __restrict__ lengths,
                                                float* __restrict__ out) {
    extern __shared__ float sm[];
    float* OV    = sm;
    float* scr   = sm + OV_F;
    float* hs    = sm + HS_OFF;
    float* sBias = sm + SB_OFF;

    unsigned sm_u  = (unsigned)__cvta_generic_to_shared(sm);
    unsigned scr_u = sm_u + OV_F * 4;

    int tid = threadIdx.x;
    int cid = blockIdx.x;
    int n   = cid;
    int b   = cid & 31, n0 = (cid >> 5) * 32;
    int grp = cid >> 5;

    int w = tid >> 5, lane = tid & 31;
    int rg = lane >> 2, co = lane & 3;
    int half = w >> 3, w8 = w & 7;

    for (int i = tid; i < 2112; i += NT) hs[i] = 0.0f;
    for (int i = tid; i < 328; i += NT) sBias[i] = g_bT[i];
    // load qkv weights ONCE (permanent for the whole run)
    for (int idx = tid; idx < 129 * 86; idx += NT) {
        int row = idx / 86, col = idx - row * 86;
        *(float4*)&OV[row * WSTR + col * 4] = *(const float4*)&g_WT2[row * WCOLS + col * 4];
    }
    __syncthreads();

    for (int tt = 0; tt <= Tn; tt++) {
        // ================= Phase A'(tt): node-major qkv (split-K) ===========
        if (tt < Tn) {
            int buf = tt & 1;
            float* combT = scr;   // 129 x 36 : combT[c][bb]
            for (int idx = tid; idx < 129 * 32; idx += NT) {
                int c = idx >> 5, bb = idx & 31;
                float v;
                if (c < Dn)       v = obs[(((size_t)bb * Tn + tt) * Nn + n) * Dn + c];
                else if (c == Dn) v = g_rar[(bb * Tn + tt) * Nn + n];
                else              v = hs[bb * 66 + (c - Dn - 1)];
                combT[c * 36 + bb] = v;
            }
            __syncthreads();

            int ch0 = 11 * w8 + co;
            int c_lo = half ? 64 : 0;
            int c_hi = half ? 129 : 64;

            unsigned long long acc[4][3][2];
            #pragma unroll
            for (int i = 0; i < 4; i++)
                #pragma unroll
                for (int j = 0; j < 3; j++) { acc[i][j][0] = 0ull; acc[i][j][1] = 0ull; }

            #pragma unroll 2
            for (int c = c_lo; c < c_hi; c++) {
                float4 zr = *(const float4*)(combT + c * 36 + rg * 4);
                const float* wr = OV + c * WSTR + ch0 * 4;
                ulonglong2 w0 = *(const ulonglong2*)(wr);
                ulonglong2 w1 = *(const ulonglong2*)(wr + 16);
                ulonglong2 w2 = *(const ulonglong2*)(wr + 32);
                #pragma unroll
                for (int i = 0; i < 4; i++) {
                    unsigned long long z2 = pk2(f4c(zr, i));
                    FMA2(acc[i][0][0], w0.x, z2); FMA2(acc[i][0][1], w0.y, z2);
                    FMA2(acc[i][1][0], w1.x, z2); FMA2(acc[i][1][1], w1.y, z2);
                    FMA2(acc[i][2][0], w2.x, z2); FMA2(acc[i][2][1], w2.y, z2);
                }
            }
            __syncthreads();   // combT dead

            if (half == 1) {
                #pragma unroll
                for (int i = 0; i < 4; i++) {
                    int row = rg * 4 + i;
                    #pragma unroll
                    for (int j = 0; j < 3; j++) {
                        if (co + 4 * j > 10) continue;
                        int ch = ch0 + 4 * j;
                        if (ch >= 82) continue;
                        float2 lo = up2(acc[i][j][0]), hi = up2(acc[i][j][1]);
                        *(float4*)&scr[row * PR + ch * 4] = make_float4(lo.x, lo.y, hi.x, hi.y);
                    }
                }
            }
            __syncthreads();

            if (half == 0) {
                float* Qb = g_Q + (size_t)buf * Bn * Nn * 32;
                float* Kb = g_K + (size_t)buf * Bn * Nn * 32;
                float* Vb = g_V + (size_t)buf * Bn * Nn * VROW;
                #pragma unroll
                for (int i = 0; i < 4; i++) {
                    int row = rg * 4 + i;
                    #pragma unroll
                    for (int j = 0; j < 3; j++) {
                        if (co + 4 * j > 10) continue;
                        int ch = ch0 + 4 * j;
                        if (ch >= 82) continue;
                        float4 part = *(const float4*)&scr[row * PR + ch * 4];
                        float2 lo = up2(acc[i][j][0]), hi = up2(acc[i][j][1]);
                        float4 bias4 = *(const float4*)&sBias[ch * 4];
                        float4 v4 = make_float4(lo.x + part.x + bias4.x,
                                                lo.y + part.y + bias4.y,
                                                hi.x + part.z + bias4.z,
                                                hi.y + part.w + bias4.w);
                        if (ch < 8)        *(float4*)&Qb[((size_t)row * Nn + n) * 32 + ch * 4] = v4;
                        else if (ch < 16)  *(float4*)&Kb[((size_t)row * Nn + n) * 32 + ch * 4 - 32] = v4;
                        else               *(float4*)&Vb[((size_t)row * Nn + n) * VROW + ch * 4 - 64] = v4;
                    }
                }
            }
        }
        if (tt == Tn) break;
        int t = tt;
        gsync(&g_ctrG, 128u * (t + 1));

        // ================= Phase B: attention (batch-major) =================
        {
            int buf = t & 1;
            float* Ks    = scr;                 // 128 x 36
            float* SsT   = scr + 4608;          // 128 x 36 (transposed P)
            float* Qs    = scr + 9216;          // 32 x 32
            float* rs    = scr + 10240;         // 128
            float* msv   = scr + 10368;         // 128
            unsigned* mskw = (unsigned*)(scr + 10496);  // 128 words
            float* v128s = scr + 10624;         // 2 x 128 (V col-128 per head)

            const float* Kg = g_K + (size_t)buf * Bn * Nn * 32 + (size_t)b * Nn * 32;
            const float* Qg = g_Q + (size_t)buf * Bn * Nn * 32 + (size_t)b * Nn * 32;
            const float* Vg = g_V + (size_t)buf * Bn * Nn * VROW + (size_t)b * Nn * VROW;

            for (int idx = tid; idx < 128 * 8; idx += NT) {
                int row = idx >> 3, q = idx & 7;
                cpa16(scr_u + (unsigned)(row * 36 + q * 4) * 4, Kg + row * 32 + q * 4);
            }
            if (tid < 256) {
                int row = tid >> 3, q = tid & 7;
                cpa16(scr_u + (unsigned)(9216 + row * 32 + q * 4) * 4, Qg + (n0 + row) * 32 + q * 4);
            }
            CP_COMMIT();

            if (tid < 128) {
                rs[tid]  = g_rar[(b * Tn + t) * Nn + tid];
                msv[tid] = maskp[((size_t)b * Tn + t) * Nn + tid];
            }
            // V column d=128 -> smem (both heads)
            if (tid < 256) {
                int hh = tid >> 7, m = tid & 127;
                v128s[hh * 128 + m] = __ldcg(Vg + hh * 132 + (size_t)m * VROW + 128);
            }
            __syncthreads();
            if (tid < 128) {
                int r = tid >> 2, ws = tid & 3;
                int nn = n0 + r;
                unsigned word = 0;
                float rn = rs[nn], mn = msv[nn];
                for (int mm = 0; mm < 32; mm++) {
                    int m = ws * 32 + mm;
                    if (nn != m) {
                        float am  = mn * msv[m];
                        float rm  = -rarW[nn * Nn + m] * fabsf(rn - rs[m]);
                        float val = g_adj[nn * Nn + m] * (1.0f + rm) * am;
                        if (val == 0.0f) word |= (1u << mm);
                    }
                }
                mskw[tid] = word;
            }
            CP_WAIT(0);
            __syncthreads();

            int r2  = tid >> 4;      // QK row 0..31
            int c16 = tid & 15;      // QK m-lane
            int chP = 4 * w8 + co;   // PV chunk 0..31
            int mlo = half * 64;     // PV m-range
            unsigned long long o[4][2];
            #pragma unroll
            for (int i = 0; i < 4; i++) { o[i][0] = 0ull; o[i][1] = 0ull; }
            float ex = 0.0f;

            for (int h = 0; h < 2; h++) {
                float4 q4[4];
                const float4* qrow = (const float4*)(Qs + r2 * 32 + h * 16);
                q4[0] = qrow[0]; q4[1] = qrow[1]; q4[2] = qrow[2]; q4[3] = qrow[3];

                float sv[8]; float mx = -3.0e38f;
                #pragma unroll
                for (int jm = 0; jm < 8; jm++) {
                    int m = c16 + 16 * jm;
                    const float4* kr = (const float4*)(Ks + m * 36 + h * 16);
                    float d = 0.0f;
                    #pragma unroll
                    for (int kq = 0; kq < 4; kq++) {
                        float4 kv = kr[kq];
                        d += q4[kq].x * kv.x + q4[kq].y * kv.y + q4[kq].z * kv.z + q4[kq].w * kv.w;
                    }
                    d *= 0.25f;
                    d = d > 0.0f ? d : 0.2f * d;
                    if ((mskw[(r2 << 2) + (m >> 5)] >> (m & 31)) & 1u) d = NEGV;
                    sv[jm] = d;
                    mx = fmaxf(mx, d);
                }
                #pragma unroll
                for (int oo = 1; oo < 16; oo <<= 1) mx = fmaxf(mx, __shfl_xor_sync(0xffffffffu, mx, oo));
                float sum = 0.0f;
                #pragma unroll
                for (int jm = 0; jm < 8; jm++) { float ee = __expf(sv[jm] - mx); sv[jm] = ee; sum += ee; }
                #pragma unroll
                for (int oo = 1; oo < 16; oo <<= 1) sum += __shfl_xor_sync(0xffffffffu, sum, oo);
                float inv = 1.0f / sum;
                #pragma unroll
                for (int jm = 0; jm < 8; jm++) SsT[(c16 + 16 * jm) * 36 + r2] = sv[jm] * inv;
                __syncthreads();

                // ---- PV: V streamed from L2 with depth-4 prefetch ----
                const float* vbase = Vg + h * 132 + (size_t)mlo * VROW + chP * 4;
                ulonglong2 pre[4];
                #pragma unroll
                for (int i = 0; i < 4; i++)
                    pre[i] = __ldcg((const ulonglong2*)(vbase + i * VROW));
                #pragma unroll 1
                for (int m4 = 0; m4 < 16; m4++) {
                    ulonglong2 cur[4];
                    #pragma unroll
                    for (int i = 0; i < 4; i++) cur[i] = pre[i];
                    if (m4 < 15) {
                        const float* nb = vbase + (size_t)(m4 + 1) * 4 * VROW;
                        #pragma unroll
                        for (int i = 0; i < 4; i++)
                            pre[i] = __ldcg((const ulonglong2*)(nb + i * VROW));
                    }
                    #pragma unroll
                    for (int i2 = 0; i2 < 4; i2++) {
                        int m = mlo + m4 * 4 + i2;
                        float4 pT = *(const float4*)(SsT + m * 36 + rg * 4);
                        unsigned long long z0 = pk2(pT.x), z1 = pk2(pT.y);
                        unsigned long long z2 = pk2(pT.z), z3 = pk2(pT.w);
                        FMA2(o[0][0], cur[i2].x, z0); FMA2(o[0][1], cur[i2].y, z0);
                        FMA2(o[1][0], cur[i2].x, z1); FMA2(o[1][1], cur[i2].y, z1);
                        FMA2(o[2][0], cur[i2].x, z2); FMA2(o[2][1], cur[i2].y, z2);
                        FMA2(o[3][0], cur[i2].x, z3); FMA2(o[3][1], cur[i2].y, z3);
                    }
                }
                if (tid < 256) {   // column d = 128
                    int row = tid >> 3, sub = tid & 7;
                    float e = 0.0f;
                    #pragma unroll
                    for (int k = 0; k < 16; k++) {
                        int m = sub * 16 + k;
                        e += SsT[m * 36 + row] * v128s[h * 128 + m];
                    }
                    ex += e;
                }
                __syncthreads();
            }
            // combine PV halves (Ks region reused, dead now)
            if (half == 1) {
                #pragma unroll
                for (int i = 0; i < 4; i++) {
                    float2 lo = up2(o[i][0]), hi = up2(o[i][1]);
                    *(float4*)&scr[((rg * 4 + i) * 32 + chP) * 4] =
                        make_float4(lo.x, lo.y, hi.x, hi.y);
                }
            }
            __syncthreads();
            if (half == 0) {
                #pragma unroll
                for (int i = 0; i < 4; i++) {
                    int nn = n0 + rg * 4 + i;
                    float4 p = *(const float4*)&scr[((rg * 4 + i) * 32 + chP) * 4];
                    float2 lo = up2(o[i][0]), hi = up2(o[i][1]);
                    float4 a = make_float4((lo.x + p.x) * 0.5f, (lo.y + p.y) * 0.5f,
                                           (hi.x + p.z) * 0.5f, (hi.y + p.w) * 0.5f);
                    *(float4*)&g_att[((size_t)b * Nn + nn) * CP + chP * 4] = a;
                }
                ex += __shfl_xor_sync(0xffffffffu, ex, 1);
                ex += __shfl_xor_sync(0xffffffffu, ex, 2);
                ex += __shfl_xor_sync(0xffffffffu, ex, 4);
                if ((tid & 7) == 0)
                    g_att[((size_t)b * Nn + n0 + (tid >> 3)) * CP + 128] = ex * 0.5f;
            }
        }
        gsync(&g_ctrGrp[grp], 32u * (t + 1));

        // ================= Phase C: gates (node-major, ring-streamed gW) ====
        {
            float* zs    = scr;                  // 32*132
            float* ring1 = scr + RING1_OFF;      // 3 x 1024
            float* h1s   = scr + 4224;           // 32*64 (post-ring)
            float* us    = scr + 6272;           // 32*64
            float* ring2 = scr + RING2_OFF;      // 3 x 512
            float* gb    = scr + GB_OFF;         // 192
            float* msk   = scr + MSK_OFF;        // 32

            const float* gwsrc = g_gW + (size_t)n * Cn * G3;

            // att -> zs (group)
            for (int idx = tid; idx < 32 * 33; idx += NT) {
                int b2 = idx / 33, q = idx - b2 * 33;
                cpa16(scr_u + (unsigned)(b2 * CP + q * 4) * 4,
                      g_att + ((size_t)b2 * Nn + n) * CP + q * 4);
            }
            CP_COMMIT();

            // ring1 blocks 0,1 (r/u cols 0..127, 8 c-rows per block)
            #define ISSUE_RU(K) do { \
                int _c0 = (K) * 8; int _rows = ((K) == 16) ? 1 : 8; \
                for (int idx = tid; idx < _rows * 32; idx += NT) { \
                    int _rr = idx >> 5, _c4 = idx & 31; \
                    cpa16(scr_u + (unsigned)(RING1_OFF + ((K) % 3) * 1024 + _rr * 128 + _c4 * 4) * 4, \
                          gwsrc + (_c0 + _rr) * G3 + _c4 * 4); \
                } CP_COMMIT(); } while (0)

            ISSUE_RU(0);
            ISSUE_RU(1);
            if (tid < G3) gb[tid] = g_gB[n * G3 + tid];
            if (tid < 32) msk[tid] = maskp[((size_t)tid * Tn + t) * Nn + n];

            int bb   = tid >> 4;
            int ch16 = tid & 15;
            bool ob = msk ? false : false;  // placeholder; read after sync
            const float* zrow = zs + bb * CP;

            // ---- r/u GEMM (ring) ----
            unsigned long long a1[2][2];
            a1[0][0] = 0ull; a1[0][1] = 0ull; a1[1][0] = 0ull; a1[1][1] = 0ull;
            for (int k = 0; k <= 16; k++) {
                if (k == 16) { CP_WAIT(0); } else { CP_WAIT(1); }
                __syncthreads();
                if (k + 2 <= 16) ISSUE_RU(k + 2);
                const float* blk = ring1 + (k % 3) * 1024;
                if (k == 16) {
                    unsigned long long z2 = pk2(zrow[128]);
                    ulonglong2 w0 = *(const ulonglong2*)(blk + ch16 * 4);
                    ulonglong2 w1 = *(const ulonglong2*)(blk + 64 + ch16 * 4);
                    FMA2(a1[0][0], w0.x, z2); FMA2(a1[0][1], w0.y, z2);
                    FMA2(a1[1][0], w1.x, z2); FMA2(a1[1][1], w1.y, z2);
                } else {
                    #pragma unroll
                    for (int rr = 0; rr < 8; rr++) {
                        unsigned long long z2 = pk2(zrow[k * 8 + rr]);
                        ulonglong2 w0 = *(const ulonglong2*)(blk + rr * 128 + ch16 * 4);
                        ulonglong2 w1 = *(const ulonglong2*)(blk + rr * 128 + 64 + ch16 * 4);
                        FMA2(a1[0][0], w0.x, z2); FMA2(a1[0][1], w0.y, z2);
                        FMA2(a1[1][0], w1.x, z2); FMA2(a1[1][1], w1.y, z2);
                    }
                }
            }
            __syncthreads();   // all ring1 reads done before h1s/us writes
            ob = msk[bb] > 0.0f;
            {
                int o0 = ch16 * 4;
                float2 lo = up2(a1[0][0]), hi = up2(a1[0][1]);
                float g0 = fsigmoid(lo.x + gb[o0 + 0]);
                float g1 = fsigmoid(lo.y + gb[o0 + 1]);
                float g2 = fsigmoid(hi.x + gb[o0 + 2]);
                float g3 = fsigmoid(hi.y + gb[o0 + 3]);
                float2 hA = *(const float2*)&hs[bb * 66 + o0];
                float2 hB = *(const float2*)&hs[bb * 66 + o0 + 2];
                float4 h1v;
                h1v.x = ob ? g0 * hA.x : hA.x;
                h1v.y = ob ? g1 * hA.y : hA.y;
                h1v.z = ob ? g2 * hB.x : hB.x;
                h1v.w = ob ? g3 * hB.y : hB.y;
                *(float4*)&h1s[bb * 64 + o0] = h1v;

                float2 lo2 = up2(a1[1][0]), hi2 = up2(a1[1][1]);
                float4 uv;
                uv.x = fsigmoid(lo2.x + gb[64 + o0 + 0]);
                uv.y = fsigmoid(lo2.y + gb[64 + o0 + 1]);
                uv.z = fsigmoid(hi2.x + gb[64 + o0 + 2]);
                uv.w = fsigmoid(hi2.y + gb[64 + o0 + 3]);
                *(float4*)&us[bb * 64 + o0] = uv;
            }
            __syncthreads();

            // zs2 = [x, h1]
            for (int idx = tid; idx < 32 * CP; idx += NT) {
                int b2 = idx / CP, c = idx - b2 * CP;
                float v = 0.0f;
                if (c < Dn)       v = obs[(((size_t)b2 * Tn + t) * Nn + n) * Dn + c];
                else if (c == Dn) v = g_rar[(b2 * Tn + t) * Nn + n];
                else if (c < Cn)  v = h1s[b2 * 64 + (c - Dn - 1)];
                zs[idx] = v;
            }
            __syncthreads();

            // ---- cand GEMM (ring2, cols 128..191) ----
            #define ISSUE_C2(K) do { \
                int _c0 = (K) * 8; int _rows = ((K) == 16) ? 1 : 8; \
                for (int idx = tid; idx < _rows * 16; idx += NT) { \
                    int _rr = idx >> 4, _c4 = idx & 15; \
                    cpa16(scr_u + (unsigned)(RING2_OFF + ((K) % 3) * 512 + _rr * 64 + _c4 * 4) * 4, \
                          gwsrc + (_c0 + _rr) * G3 + 128 + _c4 * 4); \
                } CP_COMMIT(); } while (0)

            ISSUE_C2(0);
            ISSUE_C2(1);
            unsigned long long a2[2];
            a2[0] = 0ull; a2[1] = 0ull;
            for (int k = 0; k <= 16; k++) {
                if (k == 16) { CP_WAIT(0); } else { CP_WAIT(1); }
                __syncthreads();
                if (k + 2 <= 16) ISSUE_C2(k + 2);
                const float* blk = ring2 + (k % 3) * 512;
                if (k == 16) {
                    unsigned long long z2 = pk2(zrow[128]);
                    ulonglong2 wv = *(const ulonglong2*)(blk + ch16 * 4);
                    FMA2(a2[0], wv.x, z2); FMA2(a2[1], wv.y, z2);
                } else {
                    #pragma unroll
                    for (int rr = 0; rr < 8; rr++) {
                        unsigned long long z2 = pk2(zrow[k * 8 + rr]);
                        ulonglong2 wv = *(const ulonglong2*)(blk + rr * 64 + ch16 * 4);
                        FMA2(a2[0], wv.x, z2); FMA2(a2[1], wv.y, z2);
                    }
                }
            }

            bool fin = (t == lengths[bb] - 1);
            {
                int d0 = ch16 * 4;
                float2 lo = up2(a2[0]), hi = up2(a2[1]);
                float c0 = ftanh(lo.x + gb[128 + d0 + 0]);
                float c1 = ftanh(lo.y + gb[128 + d0 + 1]);
                float c2 = ftanh(hi.x + gb[128 + d0 + 2]);
                float c3 = ftanh(hi.y + gb[128 + d0 + 3]);
                float4 h1v = *(const float4*)&h1s[bb * 64 + d0];
                float4 uv  = *(const float4*)&us[bb * 64 + d0];
                float4 h2;
                h2.x = ob ? (1.0f - uv.x) * h1v.x + uv.x * c0 : h1v.x;
                h2.y = ob ? (1.0f - uv.y) * h1v.y + uv.y * c1 : h1v.y;
                h2.z = ob ? (1.0f - uv.z) * h1v.z + uv.z * c2 : h1v.z;
                h2.w = ob ? (1.0f - uv.w) * h1v.w + uv.w * c3 : h1v.w;
                *(float2*)&hs[bb * 66 + d0]     = make_float2(h2.x, h2.y);
                *(float2*)&hs[bb * 66 + d0 + 2] = make_float2(h2.z, h2.w);
                if (fin) *(float4*)&out[((size_t)bb * Nn + n) * Dn + d0] = h2;
            }
            __syncthreads();
        }
    }
}

// ---------------- launcher ----------------
extern "C" void kernel_launch(void* const* d_in, const int* in_sizes, int n_in,
                              void* d_out, int out_size) {
    (void)n_in; (void)out_size;
    const float* obs   = (const float*)d_in[0];
    const float* maskp = (const float*)d_in[1];
    const float* avg   = (const float*)d_in[2];
    const float* plm   = (const float*)d_in[3];
    const int* lengths;
    int off;
    if (in_sizes[4] == Bn) { lengths = (const int*)d_in[4];  off = 5; }
    else                   { lengths = (const int*)d_in[25]; off = 4; }
    const float* rarW  = (const float*)d_in[off + 0];
    const float* pfW1  = (const float*)d_in[off + 1];
    const float* pfb1  = (const float*)d_in[off + 2];
    const float* pfW2  = (const float*)d_in[off + 3];
    const float* pfb2  = (const float*)d_in[off + 4];
    const float* pgW1  = (const float*)d_in[off + 5];
    const float* pgb1  = (const float*)d_in[off + 6];
    const float* pgW2  = (const float*)d_in[off + 7];
    const float* pgb2  = (const float*)d_in[off + 8];
    const float* rstW  = (const float*)d_in[off + 9];
    const float* rstB  = (const float*)d_in[off + 10];
    const float* updW  = (const float*)d_in[off + 11];
    const float* updB  = (const float*)d_in[off + 12];
    const float* candW = (const float*)d_in[off + 13];
    const float* candB = (const float*)d_in[off + 14];
    const float* qW    = (const float*)d_in[off + 15];
    const float* qb    = (const float*)d_in[off + 16];
    const float* kW    = (const float*)d_in[off + 17];
    const float* kb    = (const float*)d_in[off + 18];
    const float* vW    = (const float*)d_in[off + 19];
    const float* vb    = (const float*)d_in[off + 20];
    float* outp = (float*)d_out;

    cudaFuncSetAttribute(k_main, cudaFuncAttributeMaxDynamicSharedMemorySize, SMEM_B);

    k_preA<<<160, 128>>>(maskp, avg, plm, pfW1, pfb1, pfW2, pfb2, pgW1, pgb1, pgW2, pgb2);
    k_pre2<<<Nn, Nn>>>();
    k_preB<<<257, 352>>>(rstW, rstB, updW, updB, candW, candB, qW, qb, kW, kb, vW, vb);

    k_main<<<NCTA, NT, SMEM_B>>>(obs, maskp, rarW, lengths, outp);
}

// round 14
// speedup vs baseline: 1.0980x; 1.0980x over previous
#include <cuda_runtime.h>
#include <cstdint>

#define Bn   32
#define Tn   64
#define Nn   128
#define Dn   64
#define Cn   129
#define CP   132
#define QDn  5
#define NEn  8
#define PLMn 768
#define G3   192
#define NEGV (-9e15f)

#define WCOLS 352          // global qkv weight row stride
#define WSTR  344          // smem qkv weight row stride
#define VROW  264          // g_V row: h0 [0,129), pad, h1 [132,261)
#define NCTA  128u

// ---------------- device scratch ----------------
__device__ __align__(16) float g_qv[Nn * QDn];
__device__ __align__(16) float g_ne[Nn * NEn];
__device__ __align__(16) float g_adj[Nn * Nn];
__device__ __align__(16) float g_rar[Bn * Tn * Nn];
__device__ __align__(16) float g_gW[Nn * Cn * G3];
__device__ __align__(16) float g_gB[Nn * G3];
__device__ __align__(16) float g_WT2[Cn * WCOLS];
__device__ __align__(16) float g_bT[WCOLS];
__device__ __align__(16) float g_Q[2 * Bn * Nn * 32];
__device__ __align__(16) float g_K[2 * Bn * Nn * 32];
__device__ __align__(16) float g_V[2 * (size_t)Bn * Nn * VROW];
__device__ __align__(16) float g_att[(size_t)Bn * Nn * CP];

__device__ unsigned g_ctrG;
__device__ unsigned g_ctrGrp[4];

// ---------------- helpers ----------------
#define FMA2(acc, w, z) asm("fma.rn.f32x2 %0, %1, %2, %0;" : "+l"(acc) : "l"(w), "l"(z))

__device__ __forceinline__ unsigned long long pk2(float z) {
    unsigned long long r;
    asm("mov.b64 %0, {%1, %1};" : "=l"(r) : "f"(z));
    return r;
}
__device__ __forceinline__ float2 up2(unsigned long long v) {
    float2 r;
    asm("mov.b64 {%0, %1}, %2;" : "=f"(r.x), "=f"(r.y) : "l"(v));
    return r;
}
__device__ __forceinline__ float f4c(const float4& v, int cc) {
    return cc == 0 ? v.x : cc == 1 ? v.y : cc == 2 ? v.z : v.w;
}
__device__ __forceinline__ void cpa16(unsigned dst, const void* src) {
    asm volatile("cp.async.cg.shared.global [%0], [%1], 16;" :: "r"(dst), "l"(src));
}
#define CP_COMMIT() asm volatile("cp.async.commit_group;" ::: "memory")
#define CP_WAIT(N)  asm volatile("cp.async.wait_group %0;" :: "n"(N) : "memory")

__device__ __forceinline__ float fsigmoid(float x) {
    return __fdividef(1.0f, 1.0f + __expf(-x));
}
__device__ __forceinline__ float ftanh(float x) {
    return 1.0f - 2.0f * __fdividef(1.0f, __expf(2.0f * x) + 1.0f);
}

// ---------------- precompute ----------------
__global__ void k_preA(const float* __restrict__ maskp, const float* __restrict__ avg,
                       const float* __restrict__ plm,
                       const float* __restrict__ pfW1, const float* __restrict__ pfb1,
                       const float* __restrict__ pfW2, const float* __restrict__ pfb2,
                       const float* __restrict__ pgW1, const float* __restrict__ pgb1,
                       const float* __restrict__ pgW2, const float* __restrict__ pgb2) {
    __shared__ float h1[128], h2[128];
    __shared__ float nrm;
    if (blockIdx.x < 32) {
        int b = blockIdx.x, n = threadIdx.x;
        int gtid = b * 128 + n;
        if (gtid == 0) g_ctrG = 0;
        if (gtid < 4)  g_ctrGrp[gtid] = 0;
        float s = 0.0f;
        for (int t = 0; t < Tn; t++) s += maskp[(b * Tn + t) * Nn + n];
        float inv = 1.0f / (s + 1.0f);
        for (int t = 0; t < Tn; t++)
            g_rar[(b * Tn + t) * Nn + n] = 0.5f * tanhf(avg[(b * Tn + t) * Nn + n] * inv);
        return;
    }
    int n = blockIdx.x - 32, j = threadIdx.x;
    const float* p = plm + (size_t)n * PLMn;
    float a = 0.0f, bv = 0.0f;
    for (int c = 0; c < PLMn; c++) {
        float pv = p[c];
        a  += pv * pfW1[c * 128 + j];
        bv += pv * pgW1[c * 128 + j];
    }
    a += pfb1[j]; bv += pgb1[j];
    h1[j] = a  > 0.0f ? a  : 0.0f;
    h2[j] = bv > 0.0f ? bv : 0.0f;
    __syncthreads();
    if (j < QDn) {
        float s = pfb2[j];
        for (int c = 0; c < 128; c++) s += h1[c] * pfW2[c * QDn + j];
        g_qv[n * QDn + j] = s;
    }
    if (j < NEn) {
        float s = pgb2[j];
        for (int c = 0; c < 128; c++) s += h2[c] * pgW2[c * NEn + j];
        g_ne[n * NEn + j] = s;
    }
    __syncthreads();
    if (j == 0) {
        float s = 0.0f;
        for (int e = 0; e < NEn; e++) { float v = g_ne[n * NEn + e]; s += v * v; }
        nrm = fmaxf(sqrtf(s), 1e-12f);
    }
    __syncthreads();
    if (j < NEn) g_ne[n * NEn + j] /= nrm;
}

__global__ void k_pre2() {
    int n = blockIdx.x, m = threadIdx.x;
    __shared__ float red[128];
    float s = 0.0f;
    for (int e = 0; e < NEn; e++) s += g_ne[n * NEn + e] * g_ne[m * NEn + e];
    red[m] = s;
    __syncthreads();
    for (int st = 64; st > 0; st >>= 1) { if (m < st) red[m] = fmaxf(red[m], red[m + st]); __syncthreads(); }
    float mx = red[0];
    __syncthreads();
    float e = expf(s - mx);
    red[m] = e;
    __syncthreads();
    for (int st = 64; st > 0; st >>= 1) { if (m < st) red[m] += red[m + st]; __syncthreads(); }
    g_adj[n * Nn + m] = e / red[0];
}

__global__ void k_preB(const float* __restrict__ rstW, const float* __restrict__ rstB,
                       const float* __restrict__ updW, const float* __restrict__ updB,
                       const float* __restrict__ candW, const float* __restrict__ candB,
                       const float* __restrict__ qW, const float* __restrict__ qb,
                       const float* __restrict__ kW, const float* __restrict__ kb,
                       const float* __restrict__ vW, const float* __restrict__ vb) {
    __shared__ float qv[QDn];
    if (blockIdx.x < 128) {
        int n = blockIdx.x;
        if (threadIdx.x < QDn) qv[threadIdx.x] = g_qv[n * QDn + threadIdx.x];
        __syncthreads();
        for (int idx = threadIdx.x; idx < Cn * Dn; idx += blockDim.x) {
            int c = idx / Dn, o = idx % Dn;
            float r = 0.0f, u = 0.0f, cd = 0.0f;
            for (int q = 0; q < QDn; q++) {
                float s = qv[q];
                int off = (q * Cn + c) * Dn + o;
                r  += s * rstW[off];
                u  += s * updW[off];
                cd += s * candW[off];
            }
            float* dst = g_gW + ((size_t)n * Cn + c) * G3;
            dst[o] = r; dst[64 + o] = u; dst[128 + o] = cd;
        }
        for (int o = threadIdx.x; o < Dn; o += blockDim.x) {
            float r = 0.0f, u = 0.0f, cd = 0.0f;
            for (int q = 0; q < QDn; q++) {
                float s = qv[q];
                r  += s * rstB[q * Dn + o];
                u  += s * updB[q * Dn + o];
                cd += s * candB[q * Dn + o];
            }
            g_gB[n * G3 + o] = r; g_gB[n * G3 + 64 + o] = u; g_gB[n * G3 + 128 + o] = cd;
        }
        return;
    }
    int c = blockIdx.x - 128;
    int j = threadIdx.x;
    float w = 0.0f, bv = 0.0f;
    if (j < 32) {
        int h = j >> 4, kk = j & 15;
        w = qW[(h * Cn + c) * 16 + kk]; bv = qb[h * 16 + kk];
    } else if (j < 64) {
        int jj = j - 32; int h = jj >> 4, kk = jj & 15;
        w = kW[(h * Cn + c) * 16 + kk]; bv = kb[h * 16 + kk];
    } else if (j <= 192) {
        int d = j - 64;
        w = vW[((size_t)c) * Cn + d]; bv = vb[d];
    } else if (j >= 196 && j <= 324) {
        int d = j - 196;
        w = vW[((size_t)(Cn + c)) * Cn + d]; bv = vb[Cn + d];
    }
    g_WT2[c * WCOLS + j] = w;
    if (c == 0) g_bT[j] = bv;
}

// ---------------- group barrier ----------------
__device__ __forceinline__ void gsync(unsigned* ctr, unsigned target) {
    __syncthreads();
    if (threadIdx.x == 0) {
        __threadfence();
        atomicAdd(ctr, 1u);
        while (*(volatile unsigned*)ctr < target) { }
        __threadfence();
    }
    __syncthreads();
}

// ---------------- smem layout (floats) ----------------
#define OV_F   (Cn * WSTR)              // 44376
#define SCR_F  10624
#define HS_OFF (OV_F + SCR_F)
#define SB_OFF (HS_OFF + 2112)
#define SMEM_FLOATS (SB_OFF + 328)
#define SMEM_B (SMEM_FLOATS * 4)        // 229760 bytes

__global__ void __launch_bounds__(256, 1) k_main(const float* __restrict__ obs,
                                                 const float* __restrict__ maskp,
                                                 const float* __restrict__ rarW,
                                                 const int* __restrict__ lengths,
                                                 float* __restrict__ out) {
    extern __shared__ float sm[];
    float* OV    = sm;
    float* scr   = sm + OV_F;
    float* hs    = sm + HS_OFF;
    float* sBias = sm + SB_OFF;

    unsigned sm_u  = (unsigned)__cvta_generic_to_shared(sm);
    unsigned ov_u  = sm_u;
    unsigned scr_u = sm_u + OV_F * 4;

    int tid = threadIdx.x;
    int cid = blockIdx.x;
    int n   = cid;
    int b   = cid & 31, n0 = (cid >> 5) * 32;
    int grp = cid >> 5;

    int w = tid >> 5, lane = tid & 31;
    int rg = lane >> 2, co = lane & 3;
    int ch0 = 11 * w + co;
    int ch8 = lane >> 2;                  // (chunk, row) mapping for C

    // mask scratch (persists A -> B; A only touches scr[0..4224))
    float* rs  = scr + 10240;             // 128
    float* msv = scr + 10368;             // 128
    unsigned* mskw = (unsigned*)(scr + 10496);  // 128 words

    for (int i = tid; i < 2112; i += 256) hs[i] = 0.0f;
    for (int i = tid; i < 328; i += 256) sBias[i] = g_bT[i];
    __syncthreads();

    // prefetch qkv weights for A'(0)
    for (int idx = tid; idx < 129 * 86; idx += 256) {
        int row = idx / 86, col = idx - row * 86;
        cpa16(ov_u + (unsigned)(row * WSTR + col * 4) * 4, g_WT2 + row * WCOLS + col * 4);
    }
    CP_COMMIT();

    for (int tt = 0; tt <= Tn; tt++) {
        // ================= Phase A'(tt): node-major qkv =================
        if (tt < Tn) {
            int buf = tt & 1;
            float* comb = scr;   // 32 x 132
            for (int idx = tid; idx < 32 * CP; idx += 256) {
                int bb = idx / CP, c = idx - bb * CP;
                float v = 0.0f;
                if (c < Dn)       v = obs[(((size_t)bb * Tn + tt) * Nn + n) * Dn + c];
                else if (c == Dn) v = g_rar[(bb * Tn + tt) * Nn + n];
                else if (c < Cn)  v = hs[bb * 66 + (c - Dn - 1)];
                comb[idx] = v;
            }
            CP_WAIT(0);
            __syncthreads();

            unsigned long long acc[4][3][2];
            #pragma unroll
            for (int i = 0; i < 4; i++)
                #pragma unroll
                for (int j = 0; j < 3; j++) { acc[i][j][0] = 0ull; acc[i][j][1] = 0ull; }

            const float* zb = comb + rg * 4 * CP;
            #pragma unroll 1
            for (int c4 = 0; c4 < 32; c4++) {
                float4 z4[4];
                #pragma unroll
                for (int i = 0; i < 4; i++) z4[i] = *(const float4*)(zb + i * CP + c4 * 4);
                #pragma unroll
                for (int cc = 0; cc < 4; cc++) {
                    const float* wr = OV + (c4 * 4 + cc) * WSTR + ch0 * 4;
                    ulonglong2 w0 = *(const ulonglong2*)(wr);
                    ulonglong2 w1 = *(const ulonglong2*)(wr + 16);
                    ulonglong2 w2 = *(const ulonglong2*)(wr + 32);
                    #pragma unroll
                    for (int i = 0; i < 4; i++) {
                        unsigned long long z2 = pk2(f4c(z4[i], cc));
                        FMA2(acc[i][0][0], w0.x, z2); FMA2(acc[i][0][1], w0.y, z2);
                        FMA2(acc[i][1][0], w1.x, z2); FMA2(acc[i][1][1], w1.y, z2);
                        FMA2(acc[i][2][0], w2.x, z2); FMA2(acc[i][2][1], w2.y, z2);
                    }
                }
            }
            {   // c = 128
                const float* wr = OV + 128 * WSTR + ch0 * 4;
                ulonglong2 w0 = *(const ulonglong2*)(wr);
                ulonglong2 w1 = *(const ulonglong2*)(wr + 16);
                ulonglong2 w2 = *(const ulonglong2*)(wr + 32);
                #pragma unroll
                for (int i = 0; i < 4; i++) {
                    unsigned long long z2 = pk2(zb[i * CP + 128]);
                    FMA2(acc[i][0][0], w0.x, z2); FMA2(acc[i][0][1], w0.y, z2);
                    FMA2(acc[i][1][0], w1.x, z2); FMA2(acc[i][1][1], w1.y, z2);
                    FMA2(acc[i][2][0], w2.x, z2); FMA2(acc[i][2][1], w2.y, z2);
                }
            }
            float* Qb = g_Q + (size_t)buf * Bn * Nn * 32;
            float* Kb = g_K + (size_t)buf * Bn * Nn * 32;
            float* Vb = g_V + (size_t)buf * Bn * Nn * VROW;
            #pragma unroll
            for (int i = 0; i < 4; i++) {
                int bb = rg * 4 + i;
                #pragma unroll
                for (int j = 0; j < 3; j++) {
                    if (co + 4 * j > 10) continue;
                    int ch = ch0 + 4 * j;
                    if (ch >= 82) continue;
                    float2 lo = up2(acc[i][j][0]), hi = up2(acc[i][j][1]);
                    float4 bias4 = *(const float4*)&sBias[ch * 4];
                    float4 v4 = make_float4(lo.x + bias4.x, lo.y + bias4.y,
                                            hi.x + bias4.z, hi.y + bias4.w);
                    if (ch < 8)        *(float4*)&Qb[((size_t)bb * Nn + n) * 32 + ch * 4] = v4;
                    else if (ch < 16)  *(float4*)&Kb[((size_t)bb * Nn + n) * 32 + ch * 4 - 32] = v4;
                    else               *(float4*)&Vb[((size_t)bb * Nn + n) * VROW + ch * 4 - 64] = v4;
                }
            }
        }
        if (tt == Tn) break;
        int t = tt;

        // ---- mask precompute for B(t): overlaps A's store drain + barrier ----
        if (tid < 128) {
            rs[tid]  = g_rar[(b * Tn + t) * Nn + tid];
            msv[tid] = maskp[((size_t)b * Tn + t) * Nn + tid];
        }
        __syncthreads();
        if (tid < 128) {
            int r = tid >> 2, ws = tid & 3;
            int nn = n0 + r;
            unsigned word = 0;
            float rn = rs[nn], mn = msv[nn];
            for (int mm = 0; mm < 32; mm++) {
                int m = ws * 32 + mm;
                if (nn != m) {
                    float am  = mn * msv[m];
                    float rm  = -rarW[nn * Nn + m] * fabsf(rn - rs[m]);
                    float val = g_adj[nn * Nn + m] * (1.0f + rm) * am;
                    if (val == 0.0f) word |= (1u << mm);
                }
            }
            mskw[tid] = word;
        }
        gsync(&g_ctrG, 128u * (t + 1));

        // ================= Phase B: attention (batch-major) =================
        {
            int buf = t & 1;
            float* Vs  = OV;                 // 128 x 264
            float* Ks  = scr;                // 128 x 36
            float* SsT = scr + 4608;         // 128 x 36 (transposed P)
            float* Qs  = scr + 9216;         // 32 x 32

            const float* Kg = g_K + (size_t)buf * Bn * Nn * 32 + (size_t)b * Nn * 32;
            const float* Qg = g_Q + (size_t)buf * Bn * Nn * 32 + (size_t)b * Nn * 32;
            const float* Vg = g_V + (size_t)buf * Bn * Nn * VROW + (size_t)b * Nn * VROW;

            for (int idx = tid; idx < 128 * 8; idx += 256) {
                int row = idx >> 3, q = idx & 7;
                cpa16(scr_u + (unsigned)(row * 36 + q * 4) * 4, Kg + row * 32 + q * 4);
            }
            {
                int row = tid >> 3, q = tid & 7;
                cpa16(scr_u + (unsigned)(9216 + row * 32 + q * 4) * 4, Qg + (n0 + row) * 32 + q * 4);
            }
            CP_COMMIT();
            for (int idx = tid; idx < 128 * 66; idx += 256)
                cpa16(ov_u + (unsigned)idx * 16, Vg + idx * 4);
            CP_COMMIT();

            CP_WAIT(1);      // K + Q ready
            __syncthreads();

            int r2 = tid >> 3, c8 = tid & 7;
            int ch = 4 * w + co;
            unsigned long long o[4][2];
            #pragma unroll
            for (int i = 0; i < 4; i++) { o[i][0] = 0ull; o[i][1] = 0ull; }
            float ex = 0.0f;

            for (int h = 0; h < 2; h++) {
                float4 q4[4];
                const float4* qrow = (const float4*)(Qs + r2 * 32 + h * 16);
                q4[0] = qrow[0]; q4[1] = qrow[1]; q4[2] = qrow[2]; q4[3] = qrow[3];

                float sv[16]; float mx = -3.0e38f;
                #pragma unroll
                for (int jm = 0; jm < 16; jm++) {
                    int m = c8 + 8 * jm;
                    const float4* kr = (const float4*)(Ks + m * 36 + h * 16);
                    float d = 0.0f;
                    #pragma unroll
                    for (int kq = 0; kq < 4; kq++) {
                        float4 kv = kr[kq];
                        d += q4[kq].x * kv.x + q4[kq].y * kv.y + q4[kq].z * kv.z + q4[kq].w * kv.w;
                    }
                    d *= 0.25f;
                    d = d > 0.0f ? d : 0.2f * d;
                    if ((mskw[(r2 << 2) + (m >> 5)] >> (m & 31)) & 1u) d = NEGV;
                    sv[jm] = d;
                    mx = fmaxf(mx, d);
                }
                #pragma unroll
                for (int oo = 1; oo < 8; oo <<= 1) mx = fmaxf(mx, __shfl_xor_sync(0xffffffffu, mx, oo));
                float sum = 0.0f;
                #pragma unroll
                for (int jm = 0; jm < 16; jm++) { float ee = __expf(sv[jm] - mx); sv[jm] = ee; sum += ee; }
                #pragma unroll
                for (int oo = 1; oo < 8; oo <<= 1) sum += __shfl_xor_sync(0xffffffffu, sum, oo);
                float inv = 1.0f / sum;
                #pragma unroll
                for (int jm = 0; jm < 16; jm++) SsT[(c8 + 8 * jm) * 36 + r2] = sv[jm] * inv;
                if (h == 0) { CP_WAIT(0); }
                __syncthreads();

                const float* Vh = Vs + h * 132;
                #pragma unroll 4
                for (int m = 0; m < 128; m++) {
                    float4 pT = *(const float4*)(SsT + m * 36 + rg * 4);
                    ulonglong2 v = *(const ulonglong2*)(Vh + m * VROW + ch * 4);
                    #pragma unroll
                    for (int i = 0; i < 4; i++) {
                        unsigned long long z2 = pk2(f4c(pT, i));
                        FMA2(o[i][0], v.x, z2); FMA2(o[i][1], v.y, z2);
                    }
                }
                {   // column d = 128
                    int row = tid >> 3, sub = tid & 7;
                    float e = 0.0f;
                    #pragma unroll
                    for (int k = 0; k < 16; k++) {
                        int m = sub * 16 + k;
                        e += SsT[m * 36 + row] * Vh[m * VROW + 128];
                    }
                    ex += e;
                }
                __syncthreads();
            }
            #pragma unroll
            for (int i = 0; i < 4; i++) {
                int nn = n0 + rg * 4 + i;
                float2 lo = up2(o[i][0]), hi = up2(o[i][1]);
                float4 a = make_float4(lo.x * 0.5f, lo.y * 0.5f, hi.x * 0.5f, hi.y * 0.5f);
                *(float4*)&g_att[((size_t)b * Nn + nn) * CP + ch * 4] = a;
            }
            ex += __shfl_xor_sync(0xffffffffu, ex, 1);
            ex += __shfl_xor_sync(0xffffffffu, ex, 2);
            ex += __shfl_xor_sync(0xffffffffu, ex, 4);
            if ((tid & 7) == 0)
                g_att[((size_t)b * Nn + n0 + (tid >> 3)) * CP + 128] = ex * 0.5f;

            // prefetch C's gate weights into OV (V dead after PV + sync above)
            {
                const float* gwsrc = g_gW + (size_t)n * Cn * G3;
                for (int idx = tid; idx < Cn * G3 / 4; idx += 256)
                    cpa16(ov_u + (unsigned)idx * 16, gwsrc + idx * 4);
                CP_COMMIT();
            }
        }
        gsync(&g_ctrGrp[grp], 32u * (t + 1));

        // ================= Phase C: gates (node-major, h in smem) ===========
        {
            float* gWs = OV;              // 129*192
            float* zs  = scr;             // 32*132
            float* h1s = scr + 4224;      // 32*64
            float* us  = h1s + 2048;      // 32*64
            float* gb  = us + 2048;       // 192
            float* msk = gb + 192;        // 32

            for (int idx = tid; idx < 32 * 33; idx += 256) {
                int b2 = idx / 33, q = idx - b2 * 33;
                cpa16(scr_u + (unsigned)(b2 * CP + q * 4) * 4,
                      g_att + ((size_t)b2 * Nn + n) * CP + q * 4);
            }
            CP_COMMIT();
            if (tid < G3) gb[tid] = g_gB[n * G3 + tid];
            if (tid < 32) msk[tid] = maskp[((size_t)tid * Tn + t) * Nn + n];
            CP_WAIT(0);
            __syncthreads();

            int bb = w * 4 + (lane & 3);
            bool ob = msk[bb] > 0.0f;
            const float* zrow = zs + bb * CP;

            // ---- r/u GEMM ----
            unsigned long long a1[4][2];
            #pragma unroll
            for (int i = 0; i < 4; i++) { a1[i][0] = 0ull; a1[i][1] = 0ull; }
            #pragma unroll 2
            for (int c = 0; c < Cn; c++) {
                unsigned long long z2 = pk2(zrow[c]);
                const float* wc = gWs + c * G3 + ch8 * 4;
                #pragma unroll
                for (int rep = 0; rep < 4; rep++) {
                    ulonglong2 wv = *(const ulonglong2*)(wc + rep * 32);
                    FMA2(a1[rep][0], wv.x, z2); FMA2(a1[rep][1], wv.y, z2);
                }
            }
            #pragma unroll
            for (int rep = 0; rep < 4; rep++) {
                int o0 = (ch8 + 8 * rep) * 4;
                float2 lo = up2(a1[rep][0]), hi = up2(a1[rep][1]);
                float g0 = fsigmoid(lo.x + gb[o0 + 0]);
                float g1 = fsigmoid(lo.y + gb[o0 + 1]);
                float g2 = fsigmoid(hi.x + gb[o0 + 2]);
                float g3 = fsigmoid(hi.y + gb[o0 + 3]);
                if (rep < 2) {
                    float2 hA = *(const float2*)&hs[bb * 66 + o0];
                    float2 hB = *(const float2*)&hs[bb * 66 + o0 + 2];
                    float4 h1v;
                    h1v.x = ob ? g0 * hA.x : hA.x;
                    h1v.y = ob ? g1 * hA.y : hA.y;
                    h1v.z = ob ? g2 * hB.x : hB.x;
                    h1v.w = ob ? g3 * hB.y : hB.y;
                    *(float4*)&h1s[bb * 64 + o0] = h1v;
                } else {
                    *(float4*)&us[bb * 64 + (o0 - 64)] = make_float4(g0, g1, g2, g3);
                }
            }
            __syncthreads();

            // zs2 = [x, h1]
            for (int idx = tid; idx < 32 * CP; idx += 256) {
                int b2 = idx / CP, c = idx - b2 * CP;
                float v = 0.0f;
                if (c < Dn)       v = obs[(((size_t)b2 * Tn + t) * Nn + n) * Dn + c];
                else if (c == Dn) v = g_rar[(b2 * Tn + t) * Nn + n];
                else if (c < Cn)  v = h1s[b2 * 64 + (c - Dn - 1)];
                zs[idx] = v;
            }
            __syncthreads();

            // ---- cand GEMM ----
            unsigned long long a2[2][2];
            a2[0][0] = 0ull; a2[0][1] = 0ull; a2[1][0] = 0ull; a2[1][1] = 0ull;
            #pragma unroll 2
            for (int c = 0; c < Cn; c++) {
                unsigned long long z2 = pk2(zrow[c]);
                const float* wc = gWs + c * G3 + 128 + ch8 * 4;
                #pragma unroll
                for (int rep = 0; rep < 2; rep++) {
                    ulonglong2 wv = *(const ulonglong2*)(wc + rep * 32);
                    FMA2(a2[rep][0], wv.x, z2); FMA2(a2[rep][1], wv.y, z2);
                }
            }
            __syncthreads();   // gWs reads done

            // prefetch next A' qkv weights (overlaps epilogue)
            if (t < Tn - 1) {
                for (int idx = tid; idx < 129 * 86; idx += 256) {
                    int row = idx / 86, col = idx - row * 86;
                    cpa16(ov_u + (unsigned)(row * WSTR + col * 4) * 4,
                          g_WT2 + row * WCOLS + col * 4);
                }
                CP_COMMIT();
            }

            bool fin = (t == lengths[bb] - 1);
            #pragma unroll
            for (int rep = 0; rep < 2; rep++) {
                int d0 = (ch8 + 8 * rep) * 4;
                float2 lo = up2(a2[rep][0]), hi = up2(a2[rep][1]);
                float c0 = ftanh(lo.x + gb[128 + d0 + 0]);
                float c1 = ftanh(lo.y + gb[128 + d0 + 1]);
                float c2 = ftanh(hi.x + gb[128 + d0 + 2]);
                float c3 = ftanh(hi.y + gb[128 + d0 + 3]);
                float4 h1v = *(const float4*)&h1s[bb * 64 + d0];
                float4 uv  = *(const float4*)&us[bb * 64 + d0];
                float4 h2;
                h2.x = ob ? (1.0f - uv.x) * h1v.x + uv.x * c0 : h1v.x;
                h2.y = ob ? (1.0f - uv.y) * h1v.y + uv.y * c1 : h1v.y;
                h2.z = ob ? (1.0f - uv.z) * h1v.z + uv.z * c2 : h1v.z;
                h2.w = ob ? (1.0f - uv.w) * h1v.w + uv.w * c3 : h1v.w;
                *(float2*)&hs[bb * 66 + d0]     = make_float2(h2.x, h2.y);
                *(float2*)&hs[bb * 66 + d0 + 2] = make_float2(h2.z, h2.w);
                if (fin) *(float4*)&out[((size_t)bb * Nn + n) * Dn + d0] = h2;
            }
            __syncthreads();
        }
    }
}

// ---------------- launcher ----------------
extern "C" void kernel_launch(void* const* d_in, const int* in_sizes, int n_in,
                              void* d_out, int out_size) {
    (void)n_in; (void)out_size;
    const float* obs   = (const float*)d_in[0];
    const float* maskp = (const float*)d_in[1];
    const float* avg   = (const float*)d_in[2];
    const float* plm   = (const float*)d_in[3];
    const int* lengths;
    int off;
    if (in_sizes[4] == Bn) { lengths = (const int*)d_in[4];  off = 5; }
    else                   { lengths = (const int*)d_in[25]; off = 4; }
    const float* rarW  = (const float*)d_in[off + 0];
    const float* pfW1  = (const float*)d_in[off + 1];
    const float* pfb1  = (const float*)d_in[off + 2];
    const float* pfW2  = (const float*)d_in[off + 3];
    const float* pfb2  = (const float*)d_in[off + 4];
    const float* pgW1  = (const float*)d_in[off + 5];
    const float* pgb1  = (const float*)d_in[off + 6];
    const float* pgW2  = (const float*)d_in[off + 7];
    const float* pgb2  = (const float*)d_in[off + 8];
    const float* rstW  = (const float*)d_in[off + 9];
    const float* rstB  = (const float*)d_in[off + 10];
    const float* updW  = (const float*)d_in[off + 11];
    const float* updB  = (const float*)d_in[off + 12];
    const float* candW = (const float*)d_in[off + 13];
    const float* candB = (const float*)d_in[off + 14];
    const float* qW    = (const float*)d_in[off + 15];
    const float* qb    = (const float*)d_in[off + 16];
    const float* kW    = (const float*)d_in[off + 17];
    const float* kb    = (const float*)d_in[off + 18];
    const float* vW    = (const float*)d_in[off + 19];
    const float* vb    = (const float*)d_in[off + 20];
    float* outp = (float*)d_out;

    cudaFuncSetAttribute(k_main, cudaFuncAttributeMaxDynamicSharedMemorySize, SMEM_B);

    k_preA<<<160, 128>>>(maskp, avg, plm, pfW1, pfb1, pfW2, pfb2, pgW1, pgb1, pgW2, pgb2);
    k_pre2<<<Nn, Nn>>>();
    k_preB<<<257, 352>>>(rstW, rstB, updW, updB, candW, candB, qW, qb, kW, kb, vW, vb);

    k_main<<<NCTA, 256, SMEM_B>>>(obs, maskp, rarW, lengths, outp);
}